// round 1
// baseline (speedup 1.0000x reference)
#include <cuda_runtime.h>
#include <math_constants.h>

#define N 4096
#define D 128
#define NT 512
#define Q 8
#define NCOL 8192              // 4096 y-columns followed by 4096 x-columns
#define INV_TEMP 20.0f

// Scratch (device globals: no allocation allowed)
__device__ float  g_num[N];
__device__ float  g_den[N];
__device__ double g_loss;

// ---------------------------------------------------------------------------
// Kernel Z: zero the loss accumulator (must precede kA's atomics)
// ---------------------------------------------------------------------------
__global__ void kZ() { g_loss = 0.0; }

// ---------------------------------------------------------------------------
// Kernel A: one warp per row i.
//   sim_p[i] = min_q dot(x_i, y[track[i], q])
//   g_num[i] = exp(sim_p/T); g_den[i] = 0; g_loss -= N * sim_p/T
// ---------------------------------------------------------------------------
__global__ void kA(const float* __restrict__ x,
                   const int*   __restrict__ tidx,
                   const float* __restrict__ y) {
    int gw   = (blockIdx.x * blockDim.x + threadIdx.x) >> 5;
    int lane = threadIdx.x & 31;
    if (gw >= N) return;

    const float* xr = x + (size_t)gw * D;
    float xv0 = xr[lane];
    float xv1 = xr[lane + 32];
    float xv2 = xr[lane + 64];
    float xv3 = xr[lane + 96];

    int tr = tidx[gw];
    const float* yb = y + (size_t)tr * Q * D;

    float mn = CUDART_INF_F;
#pragma unroll
    for (int q = 0; q < Q; q++) {
        const float* yr = yb + q * D;
        float s = xv0 * yr[lane] + xv1 * yr[lane + 32]
                + xv2 * yr[lane + 64] + xv3 * yr[lane + 96];
#pragma unroll
        for (int o = 16; o > 0; o >>= 1)
            s += __shfl_xor_sync(0xffffffffu, s, o);
        mn = fminf(mn, s);
    }

    if (lane == 0) {
        float lognum = mn * INV_TEMP;        // log(num) exactly
        g_num[gw] = __expf(lognum);
        g_den[gw] = 0.0f;
        atomicAdd(&g_loss, -(double)N * (double)lognum);
    }
}

// ---------------------------------------------------------------------------
// Kernel B: fused masked-exp GEMM row reduction.
//   Virtual B matrix: cols [0,4096) = yf rows, cols [4096,8192) = x rows.
//   Tile 64x64, K=128 in two 64-chunks, 256 threads, 4x4 micro-tile,
//   f4-swizzled shared tiles (store AND read conflict-free).
// ---------------------------------------------------------------------------
__global__ __launch_bounds__(256) void kB(const float* __restrict__ x,
                                          const int*   __restrict__ tidx,
                                          const float* __restrict__ y) {
    __shared__ float4 As[64 * 16];   // [row][k4'] swizzled, 16KB
    __shared__ float4 Bs[64 * 16];   // 16KB
    __shared__ int    rts[64];
    __shared__ int    cts[64];
    __shared__ float  red[64 * 17];  // row-partial reduction, padded

    int tid = threadIdx.x;
    int tx  = tid & 15;
    int ty  = tid >> 4;
    int i0  = blockIdx.y * 64;
    int c0  = blockIdx.x * 64;

    bool is_y = (c0 < N);
    const float* Bsrc = is_y ? (y + (size_t)c0 * D)
                             : (x + (size_t)(c0 - N) * D);

    // row / column track ids
    if (tid < 64) {
        rts[tid] = tidx[i0 + tid];
    } else if (tid < 128) {
        int cc = c0 + (tid - 64);
        cts[tid - 64] = is_y ? (cc >> 3) : tidx[cc - N];
    }

    const float4* Ag = (const float4*)x   + (size_t)i0 * (D / 4);
    const float4* Bg = (const float4*)Bsrc;

    float acc[4][4];
#pragma unroll
    for (int r = 0; r < 4; r++)
#pragma unroll
        for (int c = 0; c < 4; c++) acc[r][c] = 0.0f;

    const int swA = ty >> 1;   // == ((4*ty+rr)>>3)&7 for rr in [0,4)
    const int swB = tx >> 1;

#pragma unroll
    for (int kc = 0; kc < 2; kc++) {
        // load 64x64-float chunk of each matrix, transposed-free f4 layout
#pragma unroll
        for (int it = 0; it < 4; it++) {
            int f   = tid + it * 256;        // 0..1023
            int row = f >> 4;                // 64 rows x 16 f4
            int k4  = f & 15;
            int sk  = k4 ^ ((row >> 3) & 7); // swizzle
            As[row * 16 + sk] = Ag[row * (D / 4) + kc * 16 + k4];
            Bs[row * 16 + sk] = Bg[row * (D / 4) + kc * 16 + k4];
        }
        __syncthreads();

#pragma unroll
        for (int k4 = 0; k4 < 16; k4++) {
            float4 a[4], b[4];
#pragma unroll
            for (int r = 0; r < 4; r++)
                a[r] = As[(4 * ty + r) * 16 + (k4 ^ swA)];
#pragma unroll
            for (int c = 0; c < 4; c++)
                b[c] = Bs[(4 * tx + c) * 16 + (k4 ^ swB)];
#pragma unroll
            for (int r = 0; r < 4; r++)
#pragma unroll
                for (int c = 0; c < 4; c++)
                    acc[r][c] += a[r].x * b[c].x + a[r].y * b[c].y
                               + a[r].z * b[c].z + a[r].w * b[c].w;
        }
        __syncthreads();
    }

    // epilogue: mask same-track, exp, row-sum
    int rtr[4], ctr[4];
#pragma unroll
    for (int r = 0; r < 4; r++) rtr[r] = rts[4 * ty + r];
#pragma unroll
    for (int c = 0; c < 4; c++) ctr[c] = cts[4 * tx + c];

    float rsum[4] = {0.f, 0.f, 0.f, 0.f};
#pragma unroll
    for (int r = 0; r < 4; r++)
#pragma unroll
        for (int c = 0; c < 4; c++)
            if (rtr[r] != ctr[c])
                rsum[r] += __expf(acc[r][c] * INV_TEMP);

#pragma unroll
    for (int r = 0; r < 4; r++)
        red[(4 * ty + r) * 17 + tx] = rsum[r];
    __syncthreads();

    if (tid < 64) {
        float s = 0.f;
#pragma unroll
        for (int j = 0; j < 16; j++) s += red[tid * 17 + j];
        atomicAdd(&g_den[i0 + tid], s);
    }
}

// ---------------------------------------------------------------------------
// Kernel C: g_loss += sum_{i in block-chunk, all j} log(den[j] + num[i])
//   128 blocks x 32 rows each; den cached in smem, num in registers.
// ---------------------------------------------------------------------------
__global__ void kC() {
    __shared__ float  sden[N];     // 16KB
    __shared__ double dred[256];

    int tid = threadIdx.x;
    for (int j = tid; j < N; j += 256) sden[j] = g_den[j];

    int i0 = blockIdx.x * 32;
    float nums[32];
#pragma unroll
    for (int ii = 0; ii < 32; ii++) nums[ii] = g_num[i0 + ii];
    __syncthreads();

    double dpart = 0.0;
    for (int j = tid; j < N; j += 256) {
        float dj = sden[j];
        float s  = 0.0f;
#pragma unroll
        for (int ii = 0; ii < 32; ii++)
            s += __logf(dj + nums[ii]);
        dpart += (double)s;
    }

    dred[tid] = dpart;
    __syncthreads();
    for (int off = 128; off > 0; off >>= 1) {
        if (tid < off) dred[tid] += dred[tid + off];
        __syncthreads();
    }
    if (tid == 0) atomicAdd(&g_loss, dred[0]);
}

// ---------------------------------------------------------------------------
// Kernel D: finalize
// ---------------------------------------------------------------------------
__global__ void kD(float* out) {
    out[0] = (float)(g_loss / ((double)N * (double)N));
}

// ---------------------------------------------------------------------------
extern "C" void kernel_launch(void* const* d_in, const int* in_sizes, int n_in,
                              void* d_out, int out_size) {
    const float* x    = (const float*)d_in[0];
    const int*   tidx = (const int*)  d_in[1];
    const float* y    = (const float*)d_in[2];
    float*       out  = (float*)d_out;

    kZ<<<1, 1>>>();
    kA<<<(N * 32) / 256, 256>>>(x, tidx, y);
    dim3 gB(NCOL / 64, N / 64);
    kB<<<gB, 256>>>(x, tidx, y);
    kC<<<N / 32, 256>>>();
    kD<<<1, 1>>>(out);
}

// round 3
// speedup vs baseline: 3.2390x; 3.2390x over previous
#include <cuda_runtime.h>
#include <cuda_bf16.h>
#include <math_constants.h>
#include <cstdint>

#define N 4096
#define D 128
#define NT 512
#define Q 8
#define NCOL 8192
#define INV_TEMP 20.0f

// ---------------------------------------------------------------------------
// Device scratch (no allocation allowed)
// ---------------------------------------------------------------------------
__device__ float  g_num[N];
__device__ float  g_den[N];
__device__ double g_loss;
__device__ __nv_bfloat16 g_Bh[NCOL * D];   // concat(yf, x) hi bf16
__device__ __nv_bfloat16 g_Bl[NCOL * D];   // residual lo bf16

// ---------------------------------------------------------------------------
// Helpers (base ISA only: sm_80-level features)
// ---------------------------------------------------------------------------
__device__ __forceinline__ uint32_t smem_u32(const void* p) {
    uint32_t a;
    asm("{ .reg .u64 t; cvta.to.shared.u64 t, %1; cvt.u32.u64 %0, t; }"
        : "=r"(a) : "l"(p));
    return a;
}
__device__ __forceinline__ void cpa16(uint32_t dst, const void* src) {
    asm volatile("cp.async.cg.shared.global [%0], [%1], 16;"
                 :: "r"(dst), "l"(src) : "memory");
}
__device__ __forceinline__ void cpa_commit() {
    asm volatile("cp.async.commit_group;" ::: "memory");
}
__device__ __forceinline__ void cpa_wait0() {
    asm volatile("cp.async.wait_group 0;" ::: "memory");
}
__device__ __forceinline__ void ldsm4(uint32_t* v, uint32_t addr) {
    asm volatile("ldmatrix.sync.aligned.m8n8.x4.shared.b16 {%0,%1,%2,%3}, [%4];"
                 : "=r"(v[0]), "=r"(v[1]), "=r"(v[2]), "=r"(v[3]) : "r"(addr));
}
__device__ __forceinline__ void mma16816(float* c, const uint32_t* a, const uint32_t* b) {
    asm volatile(
        "mma.sync.aligned.m16n8k16.row.col.f32.bf16.bf16.f32 "
        "{%0,%1,%2,%3}, {%4,%5,%6,%7}, {%8,%9}, {%0,%1,%2,%3};"
        : "+f"(c[0]), "+f"(c[1]), "+f"(c[2]), "+f"(c[3])
        : "r"(a[0]), "r"(a[1]), "r"(a[2]), "r"(a[3]), "r"(b[0]), "r"(b[1]));
}

// ---------------------------------------------------------------------------
// SMEM layout for kB
// ---------------------------------------------------------------------------
#define SM_AH   0
#define SM_AL   32768
#define SM_B0   65536               // buf*65536 + hl*32768
#define SM_CTS  196608              // int cts[2][128]
#define SM_RED  197632              // float red[128][2]
#define SMEM_BYTES 198656

// ---------------------------------------------------------------------------
__global__ void kZ() { g_loss = 0.0; }

// ---------------------------------------------------------------------------
// kP: convert concat(yf, x) -> (hi, lo) bf16 split
// ---------------------------------------------------------------------------
__global__ void kP(const float* __restrict__ x, const float* __restrict__ y) {
    int idx = blockIdx.x * 256 + threadIdx.x;          // float4 index
    const float4* s = (idx < (N * D / 4)) ? ((const float4*)y)
                                          : ((const float4*)x - (N * D / 4));
    float4 v = s[idx];
    __nv_bfloat16 h0 = __float2bfloat16(v.x);
    __nv_bfloat16 h1 = __float2bfloat16(v.y);
    __nv_bfloat16 h2 = __float2bfloat16(v.z);
    __nv_bfloat16 h3 = __float2bfloat16(v.w);
    __nv_bfloat16 l0 = __float2bfloat16(v.x - __bfloat162float(h0));
    __nv_bfloat16 l1 = __float2bfloat16(v.y - __bfloat162float(h1));
    __nv_bfloat16 l2 = __float2bfloat16(v.z - __bfloat162float(h2));
    __nv_bfloat16 l3 = __float2bfloat16(v.w - __bfloat162float(h3));
    __nv_bfloat162* H = (__nv_bfloat162*)g_Bh;
    __nv_bfloat162* L = (__nv_bfloat162*)g_Bl;
    H[idx * 2]     = __nv_bfloat162(h0, h1);
    H[idx * 2 + 1] = __nv_bfloat162(h2, h3);
    L[idx * 2]     = __nv_bfloat162(l0, l1);
    L[idx * 2 + 1] = __nv_bfloat162(l2, l3);
}

// ---------------------------------------------------------------------------
// kA: sim_p / num (exact fp32 path), zero g_den, subtract N*log(num)
// ---------------------------------------------------------------------------
__global__ void kA(const float* __restrict__ x,
                   const int*   __restrict__ tidx,
                   const float* __restrict__ y) {
    int gw   = (blockIdx.x * blockDim.x + threadIdx.x) >> 5;
    int lane = threadIdx.x & 31;
    if (gw >= N) return;
    const float* xr = x + (size_t)gw * D;
    float x0 = xr[lane], x1 = xr[lane + 32], x2 = xr[lane + 64], x3 = xr[lane + 96];
    const float* yb = y + (size_t)tidx[gw] * Q * D;
    float mn = CUDART_INF_F;
#pragma unroll
    for (int q = 0; q < Q; q++) {
        const float* yr = yb + q * D;
        float s = x0 * yr[lane] + x1 * yr[lane + 32] + x2 * yr[lane + 64] + x3 * yr[lane + 96];
#pragma unroll
        for (int o = 16; o > 0; o >>= 1) s += __shfl_xor_sync(0xffffffffu, s, o);
        mn = fminf(mn, s);
    }
    if (lane == 0) {
        float lognum = mn * INV_TEMP;
        g_num[gw] = __expf(lognum);
        g_den[gw] = 0.0f;
        atomicAdd(&g_loss, -(double)N * (double)lognum);
    }
}

// ---------------------------------------------------------------------------
// kB: warp-MMA (mma.sync bf16, 3-term hi/lo split) masked-exp GEMM row-sum.
//   grid (4, 32): blockIdx.y = 128-row block, blockIdx.x = 16-col-tile chunk.
//   A (hi+lo) resident in smem; B double-buffered via cp.async.
//   8 warps (4x2), warp tile 32x64 = 2x8 m16n8k16 fragments, full K=128.
// ---------------------------------------------------------------------------
__global__ __launch_bounds__(256, 1)
void kB(const int* __restrict__ tidx) {
    extern __shared__ char smem[];
    const uint32_t sb = smem_u32(smem);
    const int tid  = threadIdx.x;
    const int lane = tid & 31;
    const int wrp  = tid >> 5;
    const int wy   = wrp >> 1;            // 0..3
    const int wx   = wrp & 1;             // 0..1
    const int rb   = blockIdx.y;
    const int t0   = blockIdx.x * 16;

    int*   cts = (int*)  (smem + SM_CTS);
    float* red = (float*)(smem + SM_RED);

    // Prologue: A hi/lo + B tile 0 (cp.async), cts[0]
    {
        const uint4* AH = (const uint4*)(g_Bh + (size_t)(N + rb * 128) * D);
        const uint4* AL = (const uint4*)(g_Bl + (size_t)(N + rb * 128) * D);
        const uint4* BH = (const uint4*)(g_Bh + (size_t)t0 * 128 * D);
        const uint4* BL = (const uint4*)(g_Bl + (size_t)t0 * 128 * D);
#pragma unroll
        for (int it = 0; it < 8; it++) {
            int u = tid + it * 256;               // 2048 16B units per tile
            int r = u >> 4, c8 = u & 15;
            uint32_t phys = (uint32_t)(r * 256) + ((uint32_t)(c8 ^ (r & 7)) << 4);
            cpa16(sb + SM_AH + phys, AH + u);
            cpa16(sb + SM_AL + phys, AL + u);
            cpa16(sb + SM_B0 + phys, BH + u);
            cpa16(sb + SM_B0 + 32768 + phys, BL + u);
        }
        cpa_commit();
        if (tid < 128) {
            int cc = t0 * 128 + tid;
            cts[tid] = (cc < N) ? (cc >> 3) : __ldg(&tidx[cc - N]);
        }
    }

    // Row tracks for this thread's 4 output rows
    int rtk[2][2];
#pragma unroll
    for (int mt = 0; mt < 2; mt++)
#pragma unroll
        for (int h = 0; h < 2; h++) {
            int rl = wy * 32 + mt * 16 + (lane >> 2) + h * 8;
            rtk[mt][h] = __ldg(&tidx[rb * 128 + rl]);
        }

    // ldmatrix per-lane address precompute
    const int lr = lane & 7, g = lane >> 3;
    uint32_t arow[2], ars[2], brow[4], brs[4];
#pragma unroll
    for (int mt = 0; mt < 2; mt++) {
        int r = wy * 32 + mt * 16 + (g & 1) * 8 + lr;
        arow[mt] = (uint32_t)(r * 256); ars[mt] = (uint32_t)(r & 7);
    }
    const uint32_t akb = (uint32_t)(g >> 1);
#pragma unroll
    for (int np = 0; np < 4; np++) {
        int r = wx * 64 + np * 16 + (g >> 1) * 8 + lr;
        brow[np] = (uint32_t)(r * 256); brs[np] = (uint32_t)(r & 7);
    }
    const uint32_t bkb = (uint32_t)(g & 1);

    float rs[2][2] = {{0.f, 0.f}, {0.f, 0.f}};

    int cur = 0;
    for (int t = 0; t < 16; t++) {
        cpa_wait0();
        __syncthreads();
        int nxt = cur ^ 1;
        if (t + 1 < 16) {
            int ct = t0 + t + 1;
            const uint4* BH = (const uint4*)(g_Bh + (size_t)ct * 128 * D);
            const uint4* BL = (const uint4*)(g_Bl + (size_t)ct * 128 * D);
            uint32_t bb = sb + SM_B0 + (uint32_t)nxt * 65536u;
#pragma unroll
            for (int it = 0; it < 8; it++) {
                int u = tid + it * 256;
                int r = u >> 4, c8 = u & 15;
                uint32_t phys = (uint32_t)(r * 256) + ((uint32_t)(c8 ^ (r & 7)) << 4);
                cpa16(bb + phys, BH + u);
                cpa16(bb + 32768 + phys, BL + u);
            }
            cpa_commit();
            if (tid < 128) {
                int cc = ct * 128 + tid;
                cts[nxt * 128 + tid] = (cc < N) ? (cc >> 3) : __ldg(&tidx[cc - N]);
            }
        }

        // ---- compute 128x128 tile: 3 split products into fp32 acc ----
        float acc[2][8][4];
#pragma unroll
        for (int mt = 0; mt < 2; mt++)
#pragma unroll
            for (int nt = 0; nt < 8; nt++)
#pragma unroll
                for (int e = 0; e < 4; e++) acc[mt][nt][e] = 0.f;

        const uint32_t bcur = sb + SM_B0 + (uint32_t)cur * 65536u;
#pragma unroll
        for (int p = 0; p < 3; p++) {
            const uint32_t ab = sb + ((p < 2) ? SM_AH : SM_AL);
            const uint32_t bbk = bcur + ((p == 1) ? 32768u : 0u);
#pragma unroll
            for (int ks = 0; ks < 8; ks++) {
                uint32_t af[2][4];
#pragma unroll
                for (int mt = 0; mt < 2; mt++)
                    ldsm4(af[mt], ab + arow[mt]
                          + ((((uint32_t)(ks * 2) + akb) ^ ars[mt]) << 4));
                uint32_t bf[4][4];
#pragma unroll
                for (int np = 0; np < 4; np++)
                    ldsm4(bf[np], bbk + brow[np]
                          + ((((uint32_t)(ks * 2) + bkb) ^ brs[np]) << 4));
#pragma unroll
                for (int mt = 0; mt < 2; mt++)
#pragma unroll
                    for (int nt = 0; nt < 8; nt++)
                        mma16816(acc[mt][nt], af[mt], &bf[nt >> 1][(nt & 1) * 2]);
            }
        }

        // ---- epilogue: mask same-track, exp, accumulate per-row partials ----
        const int* ctc = cts + cur * 128;
#pragma unroll
        for (int mt = 0; mt < 2; mt++)
#pragma unroll
            for (int nt = 0; nt < 8; nt++) {
                int colb = wx * 64 + nt * 8 + (lane & 3) * 2;
                int c0t = ctc[colb], c1t = ctc[colb + 1];
                if (c0t != rtk[mt][0]) rs[mt][0] += __expf(acc[mt][nt][0] * INV_TEMP);
                if (c1t != rtk[mt][0]) rs[mt][0] += __expf(acc[mt][nt][1] * INV_TEMP);
                if (c0t != rtk[mt][1]) rs[mt][1] += __expf(acc[mt][nt][2] * INV_TEMP);
                if (c1t != rtk[mt][1]) rs[mt][1] += __expf(acc[mt][nt][3] * INV_TEMP);
            }
        cur = nxt;
    }

    // ---- final reduction: lanes sharing a row (lane&3), then the wx pair ----
#pragma unroll
    for (int mt = 0; mt < 2; mt++)
#pragma unroll
        for (int h = 0; h < 2; h++) {
            rs[mt][h] += __shfl_xor_sync(0xffffffffu, rs[mt][h], 1);
            rs[mt][h] += __shfl_xor_sync(0xffffffffu, rs[mt][h], 2);
        }
    if ((lane & 3) == 0) {
#pragma unroll
        for (int mt = 0; mt < 2; mt++)
#pragma unroll
            for (int h = 0; h < 2; h++) {
                int rl = wy * 32 + mt * 16 + (lane >> 2) + h * 8;
                red[rl * 2 + wx] = rs[mt][h];
            }
    }
    __syncthreads();
    if (tid < 128)
        atomicAdd(&g_den[rb * 128 + tid], red[tid * 2] + red[tid * 2 + 1]);
}

// ---------------------------------------------------------------------------
// kC: g_loss += sum_{i in 16-row chunk, all j} log(den[j] + num[i])
// ---------------------------------------------------------------------------
__global__ void kC() {
    __shared__ double dred[256];
    int tid = threadIdx.x;
    int i0  = blockIdx.x * 16;
    float nums[16];
#pragma unroll
    for (int ii = 0; ii < 16; ii++) nums[ii] = g_num[i0 + ii];
    double dpart = 0.0;
    for (int j = tid; j < N; j += 256) {
        float dj = __ldg(&g_den[j]);
        float s  = 0.0f;
#pragma unroll
        for (int ii = 0; ii < 16; ii++) s += __logf(dj + nums[ii]);
        dpart += (double)s;
    }
    dred[tid] = dpart;
    __syncthreads();
    for (int off = 128; off > 0; off >>= 1) {
        if (tid < off) dred[tid] += dred[tid + off];
        __syncthreads();
    }
    if (tid == 0) atomicAdd(&g_loss, dred[0]);
}

// ---------------------------------------------------------------------------
__global__ void kD(float* out) {
    out[0] = (float)(g_loss / ((double)N * (double)N));
}

// ---------------------------------------------------------------------------
extern "C" void kernel_launch(void* const* d_in, const int* in_sizes, int n_in,
                              void* d_out, int out_size) {
    const float* x    = (const float*)d_in[0];
    const int*   tidx = (const int*)  d_in[1];
    const float* y    = (const float*)d_in[2];
    float*       out  = (float*)d_out;

    cudaFuncSetAttribute(kB, cudaFuncAttributeMaxDynamicSharedMemorySize, SMEM_BYTES);

    kZ<<<1, 1>>>();
    kP<<<(NCOL * D / 4) / 256, 256>>>(x, y);
    kA<<<(N * 32) / 256, 256>>>(x, tidx, y);
    dim3 gB(4, 32);
    kB<<<gB, 256, SMEM_BYTES>>>(tidx);
    kC<<<N / 16, 256>>>();
    kD<<<1, 1>>>(out);
}